// round 6
// baseline (speedup 1.0000x reference)
#include <cuda_runtime.h>
#include <cuda_bf16.h>
#include <cstdint>

#define BB 4
#define SS 256
#define HH 768
#define N2 1536
#define MM 1024
#define NPAIR 32896

// GEMM tiling (per-batch launch: 256 rows -> grid (12, 8))
#define BM 32
#define BN 128
#define BK 32
#define RS 40                   // smem row stride in bf16 elems (80B, conflict-free)
#define APLANE (BM * RS)        // 1280 elems
#define BPLANE (BN * RS)        // 5120 elems
#define BUFSZ (2 * APLANE + 2 * BPLANE)   // 12800 elems per buffer
#define NCHUNK (HH / BK)        // 24
#define GEMM_SMEM (2 * BUFSZ * (int)sizeof(uint16_t))

__device__ float g_gv[MM * N2];   // [m][0:768)=g(+bias), [768:1536)=v

// ---------------------------------------------------------------------------
// helpers
// ---------------------------------------------------------------------------
__device__ __forceinline__ uint32_t smem_u32(const void* p) {
    uint32_t a;
    asm("{ .reg .u64 t; cvta.to.shared.u64 t, %1; cvt.u32.u64 %0, t; }" : "=r"(a) : "l"(p));
    return a;
}

__device__ __forceinline__ void ldsm_x4(uint32_t* r, uint32_t addr) {
    asm volatile("ldmatrix.sync.aligned.m8n8.x4.shared.b16 {%0,%1,%2,%3}, [%4];"
                 : "=r"(r[0]), "=r"(r[1]), "=r"(r[2]), "=r"(r[3]) : "r"(addr));
}

__device__ __forceinline__ void mma16816(float* c, const uint32_t* a, const uint32_t* b) {
    asm volatile(
        "mma.sync.aligned.m16n8k16.row.col.f32.bf16.bf16.f32 "
        "{%0,%1,%2,%3}, {%4,%5,%6,%7}, {%8,%9}, {%0,%1,%2,%3};"
        : "+f"(c[0]), "+f"(c[1]), "+f"(c[2]), "+f"(c[3])
        : "r"(a[0]), "r"(a[1]), "r"(a[2]), "r"(a[3]), "r"(b[0]), "r"(b[1]));
}

// split float4 into packed bf16 hi (leading bits) and lo (residual)
__device__ __forceinline__ void split4(float4 v, uint2& hi, uint2& lo) {
    uint32_t h0, h1;
    asm("cvt.rn.bf16x2.f32 %0, %1, %2;" : "=r"(h0) : "f"(v.y), "f"(v.x));
    asm("cvt.rn.bf16x2.f32 %0, %1, %2;" : "=r"(h1) : "f"(v.w), "f"(v.z));
    float hx = __uint_as_float(h0 << 16);
    float hy = __uint_as_float(h0 & 0xffff0000u);
    float hz = __uint_as_float(h1 << 16);
    float hw = __uint_as_float(h1 & 0xffff0000u);
    uint32_t l0, l1;
    asm("cvt.rn.bf16x2.f32 %0, %1, %2;" : "=r"(l0) : "f"(v.y - hy), "f"(v.x - hx));
    asm("cvt.rn.bf16x2.f32 %0, %1, %2;" : "=r"(l1) : "f"(v.w - hw), "f"(v.z - hz));
    hi = make_uint2(h0, h1);
    lo = make_uint2(l0, l1);
}

__device__ __forceinline__ float fast_tanh(float x) {
    float y;
    asm("tanh.approx.f32 %0, %1;" : "=f"(y) : "f"(x));
    return y;
}

// ---------------------------------------------------------------------------
// GEMM (per batch): g_gv[m][n] = sum_k X[m][k]*B[n][k] for m in [mbase, mbase+256)
// bf16 hi/lo 3-product compensation, fp32 accumulate, ldmatrix fragment loads.
// BM=32: warp tile 16x32 (2 warp-rows x 4 warp-cols).
// ---------------------------------------------------------------------------
__global__ __launch_bounds__(256, 2) void mma_gemm(
    const float* __restrict__ X, const float* __restrict__ W,
    const float* __restrict__ bias, int mbase)
{
    extern __shared__ uint16_t sm[];   // [2 bufs][Ahi|Alo|Bhi|Blo]
    const uint32_t sbase = smem_u32(sm);

    const int tid  = threadIdx.x;
    const int lane = tid & 31, wid = tid >> 5;
    const int n0 = blockIdx.x * BN;
    const int m0 = mbase + blockIdx.y * BM;
    const int side = (n0 >= HH) ? 1 : 0;
    const int wn0  = n0 - side * HH;
    const int koff = side * HH;

    const int mwB = (wid >> 2) * 16;       // warp m offset (0/16)
    const int nwB = (wid & 3) * 32;        // warp n offset (0..96)
    const int gr  = lane >> 2;             // 0..7
    const int gc  = (lane & 3) << 1;       // 0,2,4,6

    // ldmatrix lane addressing terms (elements)
    const int lrow = lane & 7;
    const int q    = lane >> 3;
    const int aTerm = (mwB + (q & 1) * 8 + lrow) * RS + (q >> 1) * 8;
    int bTerm[2];
#pragma unroll
    for (int u = 0; u < 2; u++)
        bTerm[u] = (nwB + u * 16 + (q >> 1) * 8 + lrow) * RS + (q & 1) * 8;

    // gmem<->smem slots: 1 A float4 + 4 B float4 per thread
    const float* aP;
    const float* bP[4];
    int aOff, bOff[4];
    {
        int r = tid >> 3, c = tid & 7;
        aP = X + (size_t)(m0 + r) * HH + c * 4;
        aOff = r * RS + c * 4;
    }
#pragma unroll
    for (int qq = 0; qq < 4; qq++) {
        int f = qq * 256 + tid;
        int r = f >> 3, c = f & 7;
        bP[qq] = W + (size_t)(wn0 + r) * N2 + koff + c * 4;
        bOff[qq] = r * RS + c * 4;
    }

    float acc[4][4] = {};
    float4 pa, pb[4];

    // prefetch chunk 0
    pa = *(const float4*)aP;
#pragma unroll
    for (int qq = 0; qq < 4; qq++) pb[qq] = *(const float4*)bP[qq];

#pragma unroll 1
    for (int ch = 0; ch < NCHUNK; ch++) {
        const int buf = ch & 1;
        uint16_t* D = sm + buf * BUFSZ;

        // store prefetched chunk into current buffer
        {
            uint2 hi, lo;
            split4(pa, hi, lo);
            *(uint2*)(D + 0 * APLANE + aOff) = hi;
            *(uint2*)(D + 1 * APLANE + aOff) = lo;
        }
#pragma unroll
        for (int qq = 0; qq < 4; qq++) {
            uint2 hi, lo;
            split4(pb[qq], hi, lo);
            *(uint2*)(D + 2 * APLANE + bOff[qq]) = hi;
            *(uint2*)(D + 2 * APLANE + BPLANE + bOff[qq]) = lo;
        }
        __syncthreads();

        // prefetch next chunk (overlaps with compute below)
        if (ch < NCHUNK - 1) {
            const int k0 = (ch + 1) * BK;
            pa = *(const float4*)(aP + k0);
#pragma unroll
            for (int qq = 0; qq < 4; qq++) pb[qq] = *(const float4*)(bP[qq] + k0);
        }

        // compute on current buffer
        const uint32_t Ah = sbase + (uint32_t)(buf * BUFSZ) * 2;
        const uint32_t Al = Ah + APLANE * 2;
        const uint32_t Bh = Al + APLANE * 2;
        const uint32_t Bl = Bh + BPLANE * 2;

#pragma unroll
        for (int ks = 0; ks < 2; ks++) {
            const uint32_t kb = (uint32_t)(ks * 16) * 2;
            uint32_t ahi[4], alo[4], bhi[4][2], blo[4][2];
            ldsm_x4(ahi, Ah + (uint32_t)aTerm * 2 + kb);
            ldsm_x4(alo, Al + (uint32_t)aTerm * 2 + kb);
#pragma unroll
            for (int u = 0; u < 2; u++) {
                uint32_t rh[4], rl[4];
                ldsm_x4(rh, Bh + (uint32_t)bTerm[u] * 2 + kb);
                ldsm_x4(rl, Bl + (uint32_t)bTerm[u] * 2 + kb);
                bhi[2 * u][0] = rh[0]; bhi[2 * u][1] = rh[1];
                bhi[2 * u + 1][0] = rh[2]; bhi[2 * u + 1][1] = rh[3];
                blo[2 * u][0] = rl[0]; blo[2 * u][1] = rl[1];
                blo[2 * u + 1][0] = rl[2]; blo[2 * u + 1][1] = rl[3];
            }
#pragma unroll
            for (int nt = 0; nt < 4; nt++) mma16816(acc[nt], ahi, bhi[nt]);
#pragma unroll
            for (int nt = 0; nt < 4; nt++) mma16816(acc[nt], ahi, blo[nt]);
#pragma unroll
            for (int nt = 0; nt < 4; nt++) mma16816(acc[nt], alo, bhi[nt]);
        }
    }

    // epilogue: fp32 out + bias on g half
#pragma unroll
    for (int nt = 0; nt < 4; nt++) {
        const int r = m0 + mwB + gr;
        const int c = n0 + nwB + nt * 8 + gc;
        float b0 = 0.f, b1 = 0.f;
        if (!side) { b0 = bias[c]; b1 = bias[c + 1]; }
        float* p = g_gv + (size_t)r * N2 + c;
        float2 v0, v1;
        v0.x = acc[nt][0] + b0;
        v0.y = acc[nt][1] + b1;
        v1.x = acc[nt][2] + b0;
        v1.y = acc[nt][3] + b1;
        *(float2*)p = v0;
        *(float2*)(p + 8 * N2) = v1;
    }
}

// ---------------------------------------------------------------------------
// Expansion (per batch): out[b, p(i,j), :] = tanh(g[b,i,:] + v[b,j,:])  (j >= i)
// ---------------------------------------------------------------------------
__global__ __launch_bounds__(256, 4) void expand_kernel(float* __restrict__ out, int b)
{
    constexpr int V4 = HH / 4;  // 192
    __shared__ float vs[8 * HH];

    const int i0 = blockIdx.y * 8;
    const int j0 = blockIdx.x * 8;
    if (j0 + 7 < i0) return;

    const int t = threadIdx.x;
    const int wid = t >> 5, lid = t & 31;

    // stage 8 v rows
#pragma unroll
    for (int e = t; e < 8 * V4; e += 256) {
        int r = e / V4, c = e - r * V4;
        ((float4*)vs)[e] = ((const float4*)(g_gv + (size_t)(b * SS + j0 + r) * N2 + HH))[c];
    }

    // g row for this warp -> registers (bias already folded in)
    const int i = i0 + wid;
    const float4* gsrc = (const float4*)(g_gv + (size_t)(b * SS + i) * N2);
    float4 gr4[6];
#pragma unroll
    for (int qq = 0; qq < 6; qq++) gr4[qq] = gsrc[lid + qq * 32];

    __syncthreads();

    const int pbase = i * SS - ((i * (i - 1)) >> 1) - i;  // p = pbase + j

    for (int lj = 0; lj < 8; ++lj) {
        const int j = j0 + lj;
        if (j < i) continue;
        const float4* vp = (const float4*)(vs + lj * HH);
        float4* op = (float4*)(out + ((size_t)b * NPAIR + pbase + j) * HH);
#pragma unroll
        for (int qq = 0; qq < 6; qq++) {
            const int vv = lid + qq * 32;
            float4 v4 = vp[vv];
            float4 o;
            o.x = fast_tanh(gr4[qq].x + v4.x);
            o.y = fast_tanh(gr4[qq].y + v4.y);
            o.z = fast_tanh(gr4[qq].z + v4.z);
            o.w = fast_tanh(gr4[qq].w + v4.w);
            __stcs(op + vv, o);
        }
    }
}

// ---------------------------------------------------------------------------
// launcher: per-batch GEMM on stream A, per-batch expand on stream B,
// event-gated so expand[b] overlaps gemm[b+1..3].
// ---------------------------------------------------------------------------
extern "C" void kernel_launch(void* const* d_in, const int* in_sizes, int n_in,
                              void* d_out, int out_size)
{
    const float* x    = (const float*)d_in[0];
    const float* W    = (const float*)d_in[1];
    const float* bias = (const float*)d_in[2];
    float* out = (float*)d_out;

    static cudaStream_t sA = nullptr, sB = nullptr;
    static cudaEvent_t evRoot, evG[4], evB;
    if (sA == nullptr) {   // one-time resource setup (first call is uncaptured)
        cudaStreamCreateWithFlags(&sA, cudaStreamNonBlocking);
        cudaStreamCreateWithFlags(&sB, cudaStreamNonBlocking);
        cudaEventCreateWithFlags(&evRoot, cudaEventDisableTiming);
        for (int b = 0; b < 4; b++)
            cudaEventCreateWithFlags(&evG[b], cudaEventDisableTiming);
        cudaEventCreateWithFlags(&evB, cudaEventDisableTiming);
        cudaFuncSetAttribute(mma_gemm, cudaFuncAttributeMaxDynamicSharedMemorySize,
                             GEMM_SMEM);
    }

    // fork both worker streams off the launch stream
    cudaEventRecord(evRoot, 0);
    cudaStreamWaitEvent(sA, evRoot, 0);
    cudaStreamWaitEvent(sB, evRoot, 0);

    for (int b = 0; b < 4; b++) {
        mma_gemm<<<dim3(N2 / BN, SS / BM), 256, GEMM_SMEM, sA>>>(x, W, bias, b * SS);
        cudaEventRecord(evG[b], sA);
        cudaStreamWaitEvent(sB, evG[b], 0);
        expand_kernel<<<dim3(SS / 8, SS / 8), 256, 0, sB>>>(out, b);
    }

    // join: expand[3] already depends on evG[3], so sB's tail covers everything
    cudaEventRecord(evB, sB);
    cudaStreamWaitEvent((cudaStream_t)0, evB, 0);
}

// round 7
// speedup vs baseline: 1.7039x; 1.7039x over previous
#include <cuda_runtime.h>
#include <cuda_bf16.h>
#include <cstdint>

#define BB 4
#define SS 256
#define HH 768
#define N2 1536
#define MM 1024
#define NPAIR 32896

// GEMM tiling: BM=64, BN=128, split-K=2 (each producer CTA does K=384)
#define BM 64
#define BN 128
#define BK 32
#define RS 40                   // smem row stride in bf16 elems (80B, conflict-free)
#define APLANE (BM * RS)
#define BPLANE (BN * RS)
#define BUFSZ (2 * APLANE + 2 * BPLANE)
#define NCH 12                  // chunks per K-split (384/32)
#define GEMM_SMEM (2 * BUFSZ * (int)sizeof(uint16_t))   // 61440 B
#define NGEMM 384               // 4 batches * 4 m-tiles * 12 n-tiles * 2 ksplits
#define NTILE 528               // per-batch upper-triangular 8x8 tile count

__device__ float g_gv[2][MM * N2];   // two split-K planes; [m][0:768)=g, [768:)=v
__device__ int g_cnt[16];            // per (batch, 64-row group) counters, target 24

// ---------------------------------------------------------------------------
// helpers
// ---------------------------------------------------------------------------
__device__ __forceinline__ uint32_t smem_u32(const void* p) {
    uint32_t a;
    asm("{ .reg .u64 t; cvta.to.shared.u64 t, %1; cvt.u32.u64 %0, t; }" : "=r"(a) : "l"(p));
    return a;
}

__device__ __forceinline__ void ldsm_x4(uint32_t* r, uint32_t addr) {
    asm volatile("ldmatrix.sync.aligned.m8n8.x4.shared.b16 {%0,%1,%2,%3}, [%4];"
                 : "=r"(r[0]), "=r"(r[1]), "=r"(r[2]), "=r"(r[3]) : "r"(addr));
}

__device__ __forceinline__ void mma16816(float* c, const uint32_t* a, const uint32_t* b) {
    asm volatile(
        "mma.sync.aligned.m16n8k16.row.col.f32.bf16.bf16.f32 "
        "{%0,%1,%2,%3}, {%4,%5,%6,%7}, {%8,%9}, {%0,%1,%2,%3};"
        : "+f"(c[0]), "+f"(c[1]), "+f"(c[2]), "+f"(c[3])
        : "r"(a[0]), "r"(a[1]), "r"(a[2]), "r"(a[3]), "r"(b[0]), "r"(b[1]));
}

__device__ __forceinline__ void split4(float4 v, uint2& hi, uint2& lo) {
    uint32_t h0, h1;
    asm("cvt.rn.bf16x2.f32 %0, %1, %2;" : "=r"(h0) : "f"(v.y), "f"(v.x));
    asm("cvt.rn.bf16x2.f32 %0, %1, %2;" : "=r"(h1) : "f"(v.w), "f"(v.z));
    float hx = __uint_as_float(h0 << 16);
    float hy = __uint_as_float(h0 & 0xffff0000u);
    float hz = __uint_as_float(h1 << 16);
    float hw = __uint_as_float(h1 & 0xffff0000u);
    uint32_t l0, l1;
    asm("cvt.rn.bf16x2.f32 %0, %1, %2;" : "=r"(l0) : "f"(v.y - hy), "f"(v.x - hx));
    asm("cvt.rn.bf16x2.f32 %0, %1, %2;" : "=r"(l1) : "f"(v.w - hw), "f"(v.z - hz));
    hi = make_uint2(h0, h1);
    lo = make_uint2(l0, l1);
}

__device__ __forceinline__ float fast_tanh(float x) {
    float y;
    asm("tanh.approx.f32 %0, %1;" : "=f"(y) : "f"(x));
    return y;
}

__device__ __forceinline__ int ld_acq(const int* p) {
    int v;
    asm volatile("ld.acquire.gpu.b32 %0, [%1];" : "=r"(v) : "l"(p) : "memory");
    return v;
}

// ---------------------------------------------------------------------------
__global__ void zero_cnt_kernel() {
    if (threadIdx.x < 16) g_cnt[threadIdx.x] = 0;
}

// ---------------------------------------------------------------------------
// Fused kernel.
//  bids [0, 384): GEMM producers (batch-major: bid/96 = batch)
//  bids [384, 384+4*528): expand consumers (one upper-tri 8x8 tile each)
// ---------------------------------------------------------------------------
__global__ __launch_bounds__(256, 2) void fused_kernel(
    const float* __restrict__ X, const float* __restrict__ W,
    const float* __restrict__ bias, float* __restrict__ out)
{
    extern __shared__ char smx[];
    const int bid = blockIdx.x;
    const int tid = threadIdx.x;
    const int lane = tid & 31, wid = tid >> 5;

    if (bid < NGEMM) {
        // ================= GEMM producer =================
        uint16_t* sm = (uint16_t*)smx;
        const uint32_t sbase = smem_u32(sm);

        const int b   = bid / 96;
        const int t96 = bid % 96;
        const int ksp = t96 / 48;
        const int tt  = t96 % 48;
        const int mt  = tt / 12;
        const int nt  = tt % 12;
        const int m0  = b * SS + mt * BM;
        const int n0  = nt * BN;
        const int kb0 = ksp * 384;
        const int side = (n0 >= HH) ? 1 : 0;
        const int wn0  = n0 - side * HH;
        const int koff = side * HH;

        const int mwB = (wid >> 2) * 32;
        const int nwB = (wid & 3) * 32;
        const int gr  = lane >> 2;
        const int gc  = (lane & 3) << 1;

        const int lrow = lane & 7;
        const int q    = lane >> 3;
        int aTerm[2], bTerm[2];
#pragma unroll
        for (int m = 0; m < 2; m++)
            aTerm[m] = (mwB + m * 16 + (q & 1) * 8 + lrow) * RS + (q >> 1) * 8;
#pragma unroll
        for (int u = 0; u < 2; u++)
            bTerm[u] = (nwB + u * 16 + (q >> 1) * 8 + lrow) * RS + (q & 1) * 8;

        const float* aP[2];
        const float* bP[4];
        int aOff[2], bOff[4];
#pragma unroll
        for (int qq = 0; qq < 2; qq++) {
            int f = qq * 256 + tid;
            int r = f >> 3, c = f & 7;
            aP[qq] = X + (size_t)(m0 + r) * HH + kb0 + c * 4;
            aOff[qq] = r * RS + c * 4;
        }
#pragma unroll
        for (int qq = 0; qq < 4; qq++) {
            int f = qq * 256 + tid;
            int r = f >> 3, c = f & 7;
            bP[qq] = W + (size_t)(wn0 + r) * N2 + koff + kb0 + c * 4;
            bOff[qq] = r * RS + c * 4;
        }

        float acc[2][4][4] = {};
        float4 pa[2], pb[4];

#pragma unroll
        for (int qq = 0; qq < 2; qq++) pa[qq] = *(const float4*)aP[qq];
#pragma unroll
        for (int qq = 0; qq < 4; qq++) pb[qq] = *(const float4*)bP[qq];

#pragma unroll 1
        for (int ch = 0; ch < NCH; ch++) {
            const int buf = ch & 1;
            uint16_t* D = sm + buf * BUFSZ;

#pragma unroll
            for (int qq = 0; qq < 2; qq++) {
                uint2 hi, lo;
                split4(pa[qq], hi, lo);
                *(uint2*)(D + 0 * APLANE + aOff[qq]) = hi;
                *(uint2*)(D + 1 * APLANE + aOff[qq]) = lo;
            }
#pragma unroll
            for (int qq = 0; qq < 4; qq++) {
                uint2 hi, lo;
                split4(pb[qq], hi, lo);
                *(uint2*)(D + 2 * APLANE + bOff[qq]) = hi;
                *(uint2*)(D + 2 * APLANE + BPLANE + bOff[qq]) = lo;
            }
            __syncthreads();

            if (ch < NCH - 1) {
                const int k0 = (ch + 1) * BK;
#pragma unroll
                for (int qq = 0; qq < 2; qq++) pa[qq] = *(const float4*)(aP[qq] + k0);
#pragma unroll
                for (int qq = 0; qq < 4; qq++) pb[qq] = *(const float4*)(bP[qq] + k0);
            }

            const uint32_t Ah = sbase + (uint32_t)(buf * BUFSZ) * 2;
            const uint32_t Al = Ah + APLANE * 2;
            const uint32_t Bh = Al + APLANE * 2;
            const uint32_t Bl = Bh + BPLANE * 2;

#pragma unroll
            for (int ks = 0; ks < 2; ks++) {
                const uint32_t kbb = (uint32_t)(ks * 16) * 2;
                uint32_t ahi[2][4], alo[2][4], bhi[4][2], blo[4][2];
#pragma unroll
                for (int m = 0; m < 2; m++) {
                    ldsm_x4(ahi[m], Ah + (uint32_t)aTerm[m] * 2 + kbb);
                    ldsm_x4(alo[m], Al + (uint32_t)aTerm[m] * 2 + kbb);
                }
#pragma unroll
                for (int u = 0; u < 2; u++) {
                    uint32_t rh[4], rl[4];
                    ldsm_x4(rh, Bh + (uint32_t)bTerm[u] * 2 + kbb);
                    ldsm_x4(rl, Bl + (uint32_t)bTerm[u] * 2 + kbb);
                    bhi[2 * u][0] = rh[0]; bhi[2 * u][1] = rh[1];
                    bhi[2 * u + 1][0] = rh[2]; bhi[2 * u + 1][1] = rh[3];
                    blo[2 * u][0] = rl[0]; blo[2 * u][1] = rl[1];
                    blo[2 * u + 1][0] = rl[2]; blo[2 * u + 1][1] = rl[3];
                }
#pragma unroll
                for (int m = 0; m < 2; m++)
#pragma unroll
                    for (int n = 0; n < 4; n++) mma16816(acc[m][n], ahi[m], bhi[n]);
#pragma unroll
                for (int m = 0; m < 2; m++)
#pragma unroll
                    for (int n = 0; n < 4; n++) mma16816(acc[m][n], ahi[m], blo[n]);
#pragma unroll
                for (int m = 0; m < 2; m++)
#pragma unroll
                    for (int n = 0; n < 4; n++) mma16816(acc[m][n], alo[m], bhi[n]);
            }
        }

        // epilogue -> plane ksp; bias only on (g half, plane 0)
        float* plane = g_gv[ksp];
#pragma unroll
        for (int m = 0; m < 2; m++) {
#pragma unroll
            for (int n = 0; n < 4; n++) {
                const int r = m0 + mwB + m * 16 + gr;
                const int c = n0 + nwB + n * 8 + gc;
                float b0 = 0.f, b1 = 0.f;
                if (!side && ksp == 0) { b0 = bias[c]; b1 = bias[c + 1]; }
                float* p = plane + (size_t)r * N2 + c;
                float2 v0, v1;
                v0.x = acc[m][n][0] + b0;
                v0.y = acc[m][n][1] + b1;
                v1.x = acc[m][n][2] + b0;
                v1.y = acc[m][n][3] + b1;
                *(float2*)p = v0;
                *(float2*)(p + 8 * N2) = v1;
            }
        }

        // release: make rows visible, then bump the row-group counter
        __threadfence();
        __syncthreads();
        if (tid == 0) atomicAdd(&g_cnt[b * 4 + mt], 1);

    } else {
        // ================= expand consumer =================
        constexpr int V4 = HH / 4;  // 192
        float* vs = (float*)smx;    // 8 rows * 768 floats = 24KB

        int e = bid - NGEMM;
        const int b = e / NTILE;
        int r = e % NTILE;
        int ti = 0;
        while (r >= 32 - ti) { r -= 32 - ti; ti++; }
        const int tj = ti + r;
        const int i0 = ti * 8, j0 = tj * 8;

        const int ig = b * 4 + (i0 >> 6);
        const int jg = b * 4 + (j0 >> 6);
        if (tid == 0) {
            while (ld_acq(&g_cnt[ig]) < 24) __nanosleep(64);
            while (ld_acq(&g_cnt[jg]) < 24) __nanosleep(64);
        }
        __syncthreads();

        // stage 8 v rows (sum of both split-K planes)
#pragma unroll
        for (int el = tid; el < 8 * V4; el += 256) {
            int rr = el / V4, cc = el - rr * V4;
            size_t off = (size_t)(b * SS + j0 + rr) * N2 + HH;
            float4 v0 = ((const float4*)(g_gv[0] + off))[cc];
            float4 v1 = ((const float4*)(g_gv[1] + off))[cc];
            float4 s;
            s.x = v0.x + v1.x; s.y = v0.y + v1.y;
            s.z = v0.z + v1.z; s.w = v0.w + v1.w;
            ((float4*)vs)[el] = s;
        }

        // g row for this warp -> registers (bias folded into plane 0)
        const int i = i0 + wid;
        size_t goff = (size_t)(b * SS + i) * N2;
        const float4* g0 = (const float4*)(g_gv[0] + goff);
        const float4* g1 = (const float4*)(g_gv[1] + goff);
        float4 gr4[6];
#pragma unroll
        for (int qq = 0; qq < 6; qq++) {
            float4 a = g0[lane + qq * 32], c = g1[lane + qq * 32];
            gr4[qq].x = a.x + c.x; gr4[qq].y = a.y + c.y;
            gr4[qq].z = a.z + c.z; gr4[qq].w = a.w + c.w;
        }

        __syncthreads();

        const int pbase = i * SS - ((i * (i - 1)) >> 1) - i;  // p = pbase + j

        for (int lj = 0; lj < 8; ++lj) {
            const int j = j0 + lj;
            if (j < i) continue;
            const float4* vp = (const float4*)(vs + lj * HH);
            float4* op = (float4*)(out + ((size_t)b * NPAIR + pbase + j) * HH);
#pragma unroll
            for (int qq = 0; qq < 6; qq++) {
                const int vv = lane + qq * 32;
                float4 v4 = vp[vv];
                float4 o;
                o.x = fast_tanh(gr4[qq].x + v4.x);
                o.y = fast_tanh(gr4[qq].y + v4.y);
                o.z = fast_tanh(gr4[qq].z + v4.z);
                o.w = fast_tanh(gr4[qq].w + v4.w);
                __stcs(op + vv, o);
            }
        }
    }
}

extern "C" void kernel_launch(void* const* d_in, const int* in_sizes, int n_in,
                              void* d_out, int out_size)
{
    const float* x    = (const float*)d_in[0];
    const float* W    = (const float*)d_in[1];
    const float* bias = (const float*)d_in[2];
    float* out = (float*)d_out;

    static int init = 0;
    if (!init) {
        cudaFuncSetAttribute(fused_kernel, cudaFuncAttributeMaxDynamicSharedMemorySize,
                             GEMM_SMEM);
        init = 1;
    }

    zero_cnt_kernel<<<1, 32>>>();
    fused_kernel<<<NGEMM + BB * NTILE, 256, GEMM_SMEM>>>(x, W, bias, out);
}